// round 2
// baseline (speedup 1.0000x reference)
#include <cuda_runtime.h>
#include <math.h>

#define DM    512
#define DFF   2048
#define BATCH 4
#define LSEQ  2048
#define MTOK  (BATCH * LSEQ)   // 8192 rows
#define NH    8
#define DK    64
#define EPSLN 1e-5f

// ---------------------------------------------------------------------------
// Scratch (device globals: allocation-free per harness rules)
// ---------------------------------------------------------------------------
__device__ float g_h  [(size_t)MTOK * DM];    // layernorm outputs
__device__ float g_q  [(size_t)MTOK * DM];
__device__ float g_k  [(size_t)MTOK * DM];
__device__ float g_v  [(size_t)MTOK * DM];
__device__ float g_att[(size_t)MTOK * DM];
__device__ float g_ff [(size_t)MTOK * DFF];

// ---------------------------------------------------------------------------
// LayerNorm: one block (256 threads) per row of 512
// ---------------------------------------------------------------------------
__global__ __launch_bounds__(256) void layernorm_kernel(
    const float* __restrict__ x, const float* __restrict__ g,
    const float* __restrict__ be, float* __restrict__ out)
{
    __shared__ float red[8];
    __shared__ float statv;
    int row = blockIdx.x;
    int t = threadIdx.x;
    const float* xr = x + (size_t)row * DM;

    float v0 = xr[t];
    float v1 = xr[t + 256];

    // sum
    float s = v0 + v1;
    #pragma unroll
    for (int o = 16; o; o >>= 1) s += __shfl_xor_sync(0xffffffffu, s, o);
    if ((t & 31) == 0) red[t >> 5] = s;
    __syncthreads();
    if (t == 0) {
        float tot = 0.f;
        #pragma unroll
        for (int i = 0; i < 8; i++) tot += red[i];
        statv = tot * (1.0f / DM);
    }
    __syncthreads();
    float mu = statv;
    __syncthreads();

    float d0 = v0 - mu, d1 = v1 - mu;
    s = d0 * d0 + d1 * d1;
    #pragma unroll
    for (int o = 16; o; o >>= 1) s += __shfl_xor_sync(0xffffffffu, s, o);
    if ((t & 31) == 0) red[t >> 5] = s;
    __syncthreads();
    if (t == 0) {
        float tot = 0.f;
        #pragma unroll
        for (int i = 0; i < 8; i++) tot += red[i];
        statv = rsqrtf(tot * (1.0f / DM) + EPSLN);
    }
    __syncthreads();
    float rs = statv;

    float* orow = out + (size_t)row * DM;
    orow[t]       = d0 * rs * g[t]       + be[t];
    orow[t + 256] = d1 * rs * g[t + 256] + be[t + 256];
}

// ---------------------------------------------------------------------------
// SGEMM: C[M,N] = A[M,K] @ B[K,N] + bias  (+ epilogue)
//   mode 0: bias only
//   mode 1: bias + exact GELU
//   mode 2: bias + residual add (res[M,N])
// 128x128x8 tile, 256 threads, 8x8 per thread
// ---------------------------------------------------------------------------
__device__ __forceinline__ float gelu_exact(float x) {
    return 0.5f * x * (1.0f + erff(x * 0.70710678118654752440f));
}

__global__ __launch_bounds__(256) void gemm_kernel(
    const float* __restrict__ A, const float* __restrict__ B,
    const float* __restrict__ bias, const float* __restrict__ res,
    float* __restrict__ C, int M, int N, int K, int mode)
{
    __shared__ float As[8][128];   // A^T tile
    __shared__ float Bs[8][128];

    int tid = threadIdx.x;
    int tx = tid & 15;        // 0..15 -> col block
    int ty = tid >> 4;        // 0..15 -> row block
    int bm = blockIdx.y * 128;
    int bn = blockIdx.x * 128;

    int arow = tid >> 1;              // 0..127
    int acol = (tid & 1) * 4;         // 0 or 4
    int brow = tid >> 5;              // 0..7
    int bcol = (tid & 31) * 4;        // 0..124

    float acc[8][8];
    #pragma unroll
    for (int i = 0; i < 8; i++)
        #pragma unroll
        for (int j = 0; j < 8; j++) acc[i][j] = 0.f;

    for (int k0 = 0; k0 < K; k0 += 8) {
        float4 av = *reinterpret_cast<const float4*>(
            A + (size_t)(bm + arow) * K + k0 + acol);
        float4 bv = *reinterpret_cast<const float4*>(
            B + (size_t)(k0 + brow) * N + bn + bcol);

        As[acol + 0][arow] = av.x;
        As[acol + 1][arow] = av.y;
        As[acol + 2][arow] = av.z;
        As[acol + 3][arow] = av.w;
        *reinterpret_cast<float4*>(&Bs[brow][bcol]) = bv;
        __syncthreads();

        #pragma unroll
        for (int kk = 0; kk < 8; kk++) {
            float a[8], b[8];
            *reinterpret_cast<float4*>(&a[0]) =
                *reinterpret_cast<const float4*>(&As[kk][ty * 8]);
            *reinterpret_cast<float4*>(&a[4]) =
                *reinterpret_cast<const float4*>(&As[kk][ty * 8 + 4]);
            *reinterpret_cast<float4*>(&b[0]) =
                *reinterpret_cast<const float4*>(&Bs[kk][tx * 8]);
            *reinterpret_cast<float4*>(&b[4]) =
                *reinterpret_cast<const float4*>(&Bs[kk][tx * 8 + 4]);
            #pragma unroll
            for (int i = 0; i < 8; i++)
                #pragma unroll
                for (int j = 0; j < 8; j++)
                    acc[i][j] = fmaf(a[i], b[j], acc[i][j]);
        }
        __syncthreads();
    }

    #pragma unroll
    for (int i = 0; i < 8; i++) {
        int r = bm + ty * 8 + i;
        #pragma unroll
        for (int j = 0; j < 8; j++) {
            int c = bn + tx * 8 + j;
            float v = acc[i][j] + bias[c];
            if (mode == 1) v = gelu_exact(v);
            else if (mode == 2) v += res[(size_t)r * N + c];
            C[(size_t)r * N + c] = v;
        }
    }
}

// ---------------------------------------------------------------------------
// Causal flash attention. Block = (qtile=64, head, batch), 256 threads.
// Q/K/V layout: [B*L, 512], head h occupies columns h*64..h*64+63.
// Smem: Qs + Ks + Vs = exactly 48KB. Ks uses an XOR swizzle so the 16-lane
// strided reads in the S=QK^T phase are bank-conflict-free; Ks is reused to
// stage the P tile for the PV phase.
// ---------------------------------------------------------------------------
__global__ __launch_bounds__(256) void attn_kernel(
    const float* __restrict__ Q, const float* __restrict__ K,
    const float* __restrict__ V, const int* __restrict__ mask,
    float* __restrict__ O)
{
    __shared__ float Qs[64][64];
    __shared__ float Ks[64][64];   // swizzled K; reused (plain) as P tile
    __shared__ float Vs[64][64];

    int qt = blockIdx.x, h = blockIdx.y, b = blockIdx.z;
    int q0 = qt * 64;
    int tid = threadIdx.x;
    int tx = tid & 15;   // key sub-block
    int ty = tid >> 4;   // query sub-block

    const size_t base = (size_t)b * LSEQ * DM + (size_t)h * DK;

    // load Q tile (float4, coalesced)
    #pragma unroll
    for (int it = 0; it < 4; it++) {
        int li = it * 256 + tid;         // float4 index, 0..1023
        int r = li >> 4;
        int c = (li & 15) << 2;
        *reinterpret_cast<float4*>(&Qs[r][c]) =
            *reinterpret_cast<const float4*>(Q + base + (size_t)(q0 + r) * DM + c);
    }

    float acc[4][4];
    float mrow[4], lrow[4];
    #pragma unroll
    for (int i = 0; i < 4; i++) {
        mrow[i] = -1e30f; lrow[i] = 0.f;
        #pragma unroll
        for (int j = 0; j < 4; j++) acc[i][j] = 0.f;
    }
    int fj[4];
    #pragma unroll
    for (int j = 0; j < 4; j++) {
        int r = tx * 4 + j;
        fj[j] = ((r & 3) << 4) | (r >> 2);
    }

    for (int kt = 0; kt <= qt; kt++) {
        int k0 = kt * 64;
        __syncthreads();   // previous-iter readers of Ks/Vs are done

        #pragma unroll
        for (int it = 0; it < 4; it++) {
            int li = it * 256 + tid;
            int r = li >> 4;
            int c = (li & 15) << 2;
            float4 kv4 = *reinterpret_cast<const float4*>(
                K + base + (size_t)(k0 + r) * DM + c);
            int f = ((r & 3) << 4) | (r >> 2);
            Ks[r][(c + 0) ^ f] = kv4.x;
            Ks[r][(c + 1) ^ f] = kv4.y;
            Ks[r][(c + 2) ^ f] = kv4.z;
            Ks[r][(c + 3) ^ f] = kv4.w;
            *reinterpret_cast<float4*>(&Vs[r][c]) =
                *reinterpret_cast<const float4*>(V + base + (size_t)(k0 + r) * DM + c);
        }
        __syncthreads();

        // S = Q K^T (4x4 per thread)
        float s[4][4];
        #pragma unroll
        for (int i = 0; i < 4; i++)
            #pragma unroll
            for (int j = 0; j < 4; j++) s[i][j] = 0.f;

        #pragma unroll 8
        for (int d = 0; d < 64; d++) {
            float qv[4], kv[4];
            #pragma unroll
            for (int i = 0; i < 4; i++) qv[i] = Qs[ty * 4 + i][d];
            #pragma unroll
            for (int j = 0; j < 4; j++) kv[j] = Ks[tx * 4 + j][d ^ fj[j]];
            #pragma unroll
            for (int i = 0; i < 4; i++)
                #pragma unroll
                for (int j = 0; j < 4; j++)
                    s[i][j] = fmaf(qv[i], kv[j], s[i][j]);
        }

        // scale + causal + pad mask
        #pragma unroll
        for (int j = 0; j < 4; j++) {
            int kidx = k0 + tx * 4 + j;
            int mk = mask[b * LSEQ + kidx];
            #pragma unroll
            for (int i = 0; i < 4; i++) {
                int qidx = q0 + ty * 4 + i;
                float sv = s[i][j] * 0.125f;   // 1/sqrt(64)
                if (kidx > qidx || mk == 0) sv = -1e9f;
                s[i][j] = sv;
            }
        }

        // online softmax update per row (16 lanes per row-group share a half-warp)
        #pragma unroll
        for (int i = 0; i < 4; i++) {
            float tm = s[i][0];
            #pragma unroll
            for (int j = 1; j < 4; j++) tm = fmaxf(tm, s[i][j]);
            #pragma unroll
            for (int o = 8; o; o >>= 1)
                tm = fmaxf(tm, __shfl_xor_sync(0xffffffffu, tm, o));
            float mnew = fmaxf(mrow[i], tm);
            float corr = __expf(mrow[i] - mnew);
            float rs = 0.f;
            #pragma unroll
            for (int j = 0; j < 4; j++) {
                float p = __expf(s[i][j] - mnew);
                s[i][j] = p;
                rs += p;
            }
            #pragma unroll
            for (int o = 8; o; o >>= 1)
                rs += __shfl_xor_sync(0xffffffffu, rs, o);
            lrow[i] = lrow[i] * corr + rs;
            mrow[i] = mnew;
            #pragma unroll
            for (int j = 0; j < 4; j++) acc[i][j] *= corr;
        }

        __syncthreads();   // done reading Ks (swizzled K)
        // stage P into Ks (plain layout)
        #pragma unroll
        for (int i = 0; i < 4; i++)
            #pragma unroll
            for (int j = 0; j < 4; j++)
                Ks[ty * 4 + i][tx * 4 + j] = s[i][j];
        __syncthreads();

        // O += P @ V
        #pragma unroll 8
        for (int k = 0; k < 64; k++) {
            float pv[4], vv[4];
            #pragma unroll
            for (int i = 0; i < 4; i++) pv[i] = Ks[ty * 4 + i][k];
            #pragma unroll
            for (int j = 0; j < 4; j++) vv[j] = Vs[k][tx * 4 + j];
            #pragma unroll
            for (int i = 0; i < 4; i++)
                #pragma unroll
                for (int j = 0; j < 4; j++)
                    acc[i][j] = fmaf(pv[i], vv[j], acc[i][j]);
        }
    }

    // epilogue: normalize and write
    #pragma unroll
    for (int i = 0; i < 4; i++) {
        float inv = 1.0f / lrow[i];
        #pragma unroll
        for (int j = 0; j < 4; j++) {
            O[base + (size_t)(q0 + ty * 4 + i) * DM + tx * 4 + j] = acc[i][j] * inv;
        }
    }
}

// ---------------------------------------------------------------------------
// Launch
// ---------------------------------------------------------------------------
extern "C" void kernel_launch(void* const* d_in, const int* in_sizes, int n_in,
                              void* d_out, int out_size)
{
    const float* x    = (const float*)d_in[0];
    const int*   mask = (const int*)  d_in[1];
    const float* Wq   = (const float*)d_in[2];
    const float* bq   = (const float*)d_in[3];
    const float* Wk   = (const float*)d_in[4];
    const float* bk   = (const float*)d_in[5];
    const float* Wv   = (const float*)d_in[6];
    const float* bv   = (const float*)d_in[7];
    const float* Wo   = (const float*)d_in[8];
    const float* bo   = (const float*)d_in[9];
    const float* g1   = (const float*)d_in[10];
    const float* be1  = (const float*)d_in[11];
    const float* g2   = (const float*)d_in[12];
    const float* be2  = (const float*)d_in[13];
    const float* W1   = (const float*)d_in[14];
    const float* b1   = (const float*)d_in[15];
    const float* W2   = (const float*)d_in[16];
    const float* b2   = (const float*)d_in[17];
    float* out = (float*)d_out;

    float *h, *q, *k, *v, *att, *ff;
    cudaGetSymbolAddress((void**)&h,   g_h);
    cudaGetSymbolAddress((void**)&q,   g_q);
    cudaGetSymbolAddress((void**)&k,   g_k);
    cudaGetSymbolAddress((void**)&v,   g_v);
    cudaGetSymbolAddress((void**)&att, g_att);
    cudaGetSymbolAddress((void**)&ff,  g_ff);

    // 1. ln1(x) -> h
    layernorm_kernel<<<MTOK, 256>>>(x, g1, be1, h);

    // 2-4. Q/K/V projections
    dim3 gproj(DM / 128, MTOK / 128);
    gemm_kernel<<<gproj, 256>>>(h, Wq, bq, nullptr, q, MTOK, DM, DM, 0);
    gemm_kernel<<<gproj, 256>>>(h, Wk, bk, nullptr, k, MTOK, DM, DM, 0);
    gemm_kernel<<<gproj, 256>>>(h, Wv, bv, nullptr, v, MTOK, DM, DM, 0);

    // 5. causal attention -> att
    dim3 gattn(LSEQ / 64, NH, BATCH);
    attn_kernel<<<gattn, 256>>>(q, k, v, mask, att);

    // 6. O projection + residual(x) -> out (= x2)
    gemm_kernel<<<gproj, 256>>>(att, Wo, bo, x, out, MTOK, DM, DM, 2);

    // 7. ln2(out) -> h
    layernorm_kernel<<<MTOK, 256>>>(out, g2, be2, h);

    // 8. FFN1 + GELU -> ff
    dim3 gff1(DFF / 128, MTOK / 128);
    gemm_kernel<<<gff1, 256>>>(h, W1, b1, nullptr, ff, MTOK, DFF, DM, 1);

    // 9. FFN2 + residual(out) -> out
    dim3 gff2(DM / 128, MTOK / 128);
    gemm_kernel<<<gff2, 256>>>(ff, W2, b2, out, out, MTOK, DM, DFF, 2);
}

// round 4
// speedup vs baseline: 1.8923x; 1.8923x over previous
#include <cuda_runtime.h>
#include <cstdint>
#include <math.h>

#define DM    512
#define DFF   2048
#define BATCH 4
#define LSEQ  2048
#define MTOK  (BATCH * LSEQ)   // 8192 rows
#define NH    8
#define DK    64
#define EPSLN 1e-5f

// ---------------------------------------------------------------------------
// Scratch (device globals: allocation-free per harness rules)
// ---------------------------------------------------------------------------
__device__ float g_h  [(size_t)MTOK * DM];    // layernorm outputs (tf32-rounded)
__device__ float g_q  [(size_t)MTOK * DM];
__device__ float g_k  [(size_t)MTOK * DM];
__device__ float g_v  [(size_t)MTOK * DM];
__device__ float g_att[(size_t)MTOK * DM];    // attention out (tf32-rounded)
__device__ float g_ff [(size_t)MTOK * DFF];   // gelu out (tf32-rounded)
// transposed + tf32-rounded weights
__device__ float g_wt [4 * 512 * 512 + 2 * 512 * 2048];

#define WT_Q  0
#define WT_K  (512*512)
#define WT_V  (2*512*512)
#define WT_O  (3*512*512)
#define WT_1  (4*512*512)
#define WT_2  (4*512*512 + 512*2048)

// ---------------------------------------------------------------------------
// PTX helpers (baseline PTX only: works under compute_103 target)
// ---------------------------------------------------------------------------
__device__ __forceinline__ uint32_t smem_u32(const void* p) {
    uint32_t a;
    asm("{ .reg .u64 t; cvta.to.shared.u64 t, %1; cvt.u32.u64 %0, t; }" : "=r"(a) : "l"(p));
    return a;
}
__device__ __forceinline__ float f_rna_tf32(float x) {
    uint32_t u;
    asm("cvt.rna.tf32.f32 %0, %1;" : "=r"(u) : "f"(x));
    return __uint_as_float(u);
}

#define CP_ASYNC16(dst, src) \
    asm volatile("cp.async.cg.shared.global [%0], [%1], 16;" :: "r"(dst), "l"(src))
#define CP_COMMIT() asm volatile("cp.async.commit_group;" ::: "memory")
#define CP_WAIT1()  asm volatile("cp.async.wait_group 1;" ::: "memory")

__device__ __forceinline__ void mma_tf32(
    float& d0, float& d1, float& d2, float& d3,
    uint32_t a0, uint32_t a1, uint32_t a2, uint32_t a3,
    uint32_t b0, uint32_t b1)
{
    asm volatile(
        "mma.sync.aligned.m16n8k8.row.col.f32.tf32.tf32.f32 "
        "{%0,%1,%2,%3}, {%4,%5,%6,%7}, {%8,%9}, {%0,%1,%2,%3};"
        : "+f"(d0), "+f"(d1), "+f"(d2), "+f"(d3)
        : "r"(a0), "r"(a1), "r"(a2), "r"(a3), "r"(b0), "r"(b1));
}

__device__ __forceinline__ float gelu_exact(float x) {
    return 0.5f * x * (1.0f + erff(x * 0.70710678118654752440f));
}

// ---------------------------------------------------------------------------
// LayerNorm: one block (256 threads) per row of 512. rnd=1 -> tf32-round out.
// ---------------------------------------------------------------------------
__global__ __launch_bounds__(256) void layernorm_kernel(
    const float* __restrict__ x, const float* __restrict__ g,
    const float* __restrict__ be, float* __restrict__ out, int rnd)
{
    __shared__ float red[8];
    __shared__ float statv;
    int row = blockIdx.x;
    int t = threadIdx.x;
    const float* xr = x + (size_t)row * DM;

    float v0 = xr[t];
    float v1 = xr[t + 256];

    float s = v0 + v1;
    #pragma unroll
    for (int o = 16; o; o >>= 1) s += __shfl_xor_sync(0xffffffffu, s, o);
    if ((t & 31) == 0) red[t >> 5] = s;
    __syncthreads();
    if (t == 0) {
        float tot = 0.f;
        #pragma unroll
        for (int i = 0; i < 8; i++) tot += red[i];
        statv = tot * (1.0f / DM);
    }
    __syncthreads();
    float mu = statv;
    __syncthreads();

    float d0 = v0 - mu, d1 = v1 - mu;
    s = d0 * d0 + d1 * d1;
    #pragma unroll
    for (int o = 16; o; o >>= 1) s += __shfl_xor_sync(0xffffffffu, s, o);
    if ((t & 31) == 0) red[t >> 5] = s;
    __syncthreads();
    if (t == 0) {
        float tot = 0.f;
        #pragma unroll
        for (int i = 0; i < 8; i++) tot += red[i];
        statv = rsqrtf(tot * (1.0f / DM) + EPSLN);
    }
    __syncthreads();
    float rs = statv;

    float o0 = d0 * rs * g[t]       + be[t];
    float o1 = d1 * rs * g[t + 256] + be[t + 256];
    if (rnd) { o0 = f_rna_tf32(o0); o1 = f_rna_tf32(o1); }
    float* orow = out + (size_t)row * DM;
    orow[t]       = o0;
    orow[t + 256] = o1;
}

// ---------------------------------------------------------------------------
// Weight transpose + round-to-tf32.  in: [R][C] -> out: [C][R]
// ---------------------------------------------------------------------------
__global__ __launch_bounds__(256) void transpose_rna_kernel(
    const float* __restrict__ in, float* __restrict__ out, int R, int C)
{
    __shared__ float t[32][33];
    int bx = blockIdx.x * 32;   // over C
    int by = blockIdx.y * 32;   // over R
    int txl = threadIdx.x, tyl = threadIdx.y;  // 32 x 8
    #pragma unroll
    for (int i = 0; i < 32; i += 8)
        t[tyl + i][txl] = in[(size_t)(by + tyl + i) * C + bx + txl];
    __syncthreads();
    #pragma unroll
    for (int i = 0; i < 32; i += 8)
        out[(size_t)(bx + tyl + i) * R + by + txl] = f_rna_tf32(t[txl][tyl + i]);
}

// ---------------------------------------------------------------------------
// Tensor-core tf32 GEMM via mma.sync (legacy HMMA path, baseline PTX):
//   C[M,N] = A[M,K] @ BT[N,K]^T + bias (+ epilogue)
//   mode 0: bias; 1: bias+GELU (tf32-rounded); 2: bias+residual
// CTA tile 128x128, K-chunk 32, 2-stage cp.async pipeline, 256 threads.
// Warp layout 2(M)x4(N); warp tile 64x32 = 4x4 m16n8k8 frags.
// A and BT must be PRE-ROUNDED to tf32 by producers.
// ---------------------------------------------------------------------------
#define ROWPAD 36
#define STG_FLOATS (128 * ROWPAD)               // per operand per stage
#define SMEM_GEMM (2 * 2 * STG_FLOATS * 4)      // 73728 bytes

__global__ __launch_bounds__(256, 2) void gemm_tc_kernel(
    const float* __restrict__ A, const float* __restrict__ BT,
    const float* __restrict__ bias, const float* __restrict__ res,
    float* __restrict__ C, int M, int N, int K, int mode)
{
    extern __shared__ float smem[];
    const uint32_t sb = smem_u32(smem);
    const int tid = threadIdx.x;
    const int wid = tid >> 5;
    const int lid = tid & 31;
    const int g = lid >> 2;      // 0..7
    const int t = lid & 3;       // 0..3
    const int bm = blockIdx.y * 128;
    const int bn = blockIdx.x * 128;
    const int m_off = (wid & 1) * 64;
    const int n_off = (wid >> 1) * 32;
    const int nchunk = K >> 5;

    float d[4][4][4];
    #pragma unroll
    for (int mf = 0; mf < 4; mf++)
        #pragma unroll
        for (int nf = 0; nf < 4; nf++)
            #pragma unroll
            for (int r = 0; r < 4; r++) d[mf][nf][r] = 0.f;

    // per-thread cp.async source/dest (8 transfers of 16B per stage)
    // u in [0,2048): op=u>>10, row=(u&1023)>>3, c4=u&7
    auto issue = [&](int c, int s) {
        const int k0 = c << 5;
        const uint32_t sbase = sb + (uint32_t)(s * 2 * STG_FLOATS) * 4u;
        #pragma unroll
        for (int it = 0; it < 8; it++) {
            int u = it * 256 + tid;
            int op = u >> 10;
            int v = u & 1023;
            int row = v >> 3;
            int c4 = v & 7;
            const float* src = op
                ? (BT + (size_t)(bn + row) * K + k0 + (c4 << 2))
                : (A  + (size_t)(bm + row) * K + k0 + (c4 << 2));
            uint32_t dst = sbase + (uint32_t)(op * STG_FLOATS + row * ROWPAD + (c4 << 2)) * 4u;
            CP_ASYNC16(dst, src);
        }
    };

    issue(0, 0);
    CP_COMMIT();

    int buf = 0;
    for (int c = 0; c < nchunk; c++) {
        if (c + 1 < nchunk) issue(c + 1, buf ^ 1);
        CP_COMMIT();
        CP_WAIT1();
        __syncthreads();

        const uint32_t* sAu = (const uint32_t*)smem + buf * 2 * STG_FLOATS;
        const uint32_t* sBu = sAu + STG_FLOATS;
        // base row indices for this thread's fragments
        const int arow = (m_off + g) * ROWPAD + t;
        const int brow = (n_off + g) * ROWPAD + t;

        #pragma unroll
        for (int kk = 0; kk < 32; kk += 8) {
            uint32_t a[4][4], b[4][2];
            #pragma unroll
            for (int mf = 0; mf < 4; mf++) {
                int base = arow + mf * 16 * ROWPAD + kk;
                a[mf][0] = sAu[base];
                a[mf][1] = sAu[base + 8 * ROWPAD];
                a[mf][2] = sAu[base + 4];
                a[mf][3] = sAu[base + 8 * ROWPAD + 4];
            }
            #pragma unroll
            for (int nf = 0; nf < 4; nf++) {
                int base = brow + nf * 8 * ROWPAD + kk;
                b[nf][0] = sBu[base];
                b[nf][1] = sBu[base + 4];
            }
            #pragma unroll
            for (int mf = 0; mf < 4; mf++)
                #pragma unroll
                for (int nf = 0; nf < 4; nf++)
                    mma_tf32(d[mf][nf][0], d[mf][nf][1], d[mf][nf][2], d[mf][nf][3],
                             a[mf][0], a[mf][1], a[mf][2], a[mf][3],
                             b[nf][0], b[nf][1]);
        }
        __syncthreads();
        buf ^= 1;
    }

    // ---- epilogue: registers -> gmem (float2 per fragment half) ----
    #pragma unroll
    for (int nf = 0; nf < 4; nf++) {
        int col = bn + n_off + nf * 8 + 2 * t;
        float2 bi = *reinterpret_cast<const float2*>(bias + col);
        #pragma unroll
        for (int mf = 0; mf < 4; mf++) {
            int r0 = bm + m_off + mf * 16 + g;
            #pragma unroll
            for (int half = 0; half < 2; half++) {
                int r = r0 + half * 8;
                float v0 = d[mf][nf][half * 2 + 0] + bi.x;
                float v1 = d[mf][nf][half * 2 + 1] + bi.y;
                if (mode == 1) {
                    v0 = f_rna_tf32(gelu_exact(v0));
                    v1 = f_rna_tf32(gelu_exact(v1));
                } else if (mode == 2) {
                    float2 rv = *reinterpret_cast<const float2*>(
                        res + (size_t)r * N + col);
                    v0 += rv.x; v1 += rv.y;
                }
                float2 o; o.x = v0; o.y = v1;
                *reinterpret_cast<float2*>(C + (size_t)r * N + col) = o;
            }
        }
    }
}

// ---------------------------------------------------------------------------
// Causal flash attention (fp32 scalar). Output tf32-rounded (feeds O-proj).
// ---------------------------------------------------------------------------
__global__ __launch_bounds__(256) void attn_kernel(
    const float* __restrict__ Q, const float* __restrict__ K,
    const float* __restrict__ V, const int* __restrict__ mask,
    float* __restrict__ O)
{
    __shared__ float Qs[64][64];
    __shared__ float Ks[64][64];
    __shared__ float Vs[64][64];

    int qt = blockIdx.x, h = blockIdx.y, b = blockIdx.z;
    int q0 = qt * 64;
    int tid = threadIdx.x;
    int tx = tid & 15;
    int ty = tid >> 4;

    const size_t base = (size_t)b * LSEQ * DM + (size_t)h * DK;

    #pragma unroll
    for (int it = 0; it < 4; it++) {
        int li = it * 256 + tid;
        int r = li >> 4;
        int c = (li & 15) << 2;
        *reinterpret_cast<float4*>(&Qs[r][c]) =
            *reinterpret_cast<const float4*>(Q + base + (size_t)(q0 + r) * DM + c);
    }

    float acc[4][4];
    float mrow[4], lrow[4];
    #pragma unroll
    for (int i = 0; i < 4; i++) {
        mrow[i] = -1e30f; lrow[i] = 0.f;
        #pragma unroll
        for (int j = 0; j < 4; j++) acc[i][j] = 0.f;
    }
    int fj[4];
    #pragma unroll
    for (int j = 0; j < 4; j++) {
        int r = tx * 4 + j;
        fj[j] = ((r & 3) << 4) | (r >> 2);
    }

    for (int kt = 0; kt <= qt; kt++) {
        int k0 = kt * 64;
        __syncthreads();

        #pragma unroll
        for (int it = 0; it < 4; it++) {
            int li = it * 256 + tid;
            int r = li >> 4;
            int c = (li & 15) << 2;
            float4 kv4 = *reinterpret_cast<const float4*>(
                K + base + (size_t)(k0 + r) * DM + c);
            int f = ((r & 3) << 4) | (r >> 2);
            Ks[r][(c + 0) ^ f] = kv4.x;
            Ks[r][(c + 1) ^ f] = kv4.y;
            Ks[r][(c + 2) ^ f] = kv4.z;
            Ks[r][(c + 3) ^ f] = kv4.w;
            *reinterpret_cast<float4*>(&Vs[r][c]) =
                *reinterpret_cast<const float4*>(V + base + (size_t)(k0 + r) * DM + c);
        }
        __syncthreads();

        float s[4][4];
        #pragma unroll
        for (int i = 0; i < 4; i++)
            #pragma unroll
            for (int j = 0; j < 4; j++) s[i][j] = 0.f;

        #pragma unroll 8
        for (int d = 0; d < 64; d++) {
            float qv[4], kv[4];
            #pragma unroll
            for (int i = 0; i < 4; i++) qv[i] = Qs[ty * 4 + i][d];
            #pragma unroll
            for (int j = 0; j < 4; j++) kv[j] = Ks[tx * 4 + j][d ^ fj[j]];
            #pragma unroll
            for (int i = 0; i < 4; i++)
                #pragma unroll
                for (int j = 0; j < 4; j++)
                    s[i][j] = fmaf(qv[i], kv[j], s[i][j]);
        }

        #pragma unroll
        for (int j = 0; j < 4; j++) {
            int kidx = k0 + tx * 4 + j;
            int mk = mask[b * LSEQ + kidx];
            #pragma unroll
            for (int i = 0; i < 4; i++) {
                int qidx = q0 + ty * 4 + i;
                float sv = s[i][j] * 0.125f;
                if (kidx > qidx || mk == 0) sv = -1e9f;
                s[i][j] = sv;
            }
        }

        #pragma unroll
        for (int i = 0; i < 4; i++) {
            float tm = s[i][0];
            #pragma unroll
            for (int j = 1; j < 4; j++) tm = fmaxf(tm, s[i][j]);
            #pragma unroll
            for (int o = 8; o; o >>= 1)
                tm = fmaxf(tm, __shfl_xor_sync(0xffffffffu, tm, o));
            float mnew = fmaxf(mrow[i], tm);
            float corr = __expf(mrow[i] - mnew);
            float rs = 0.f;
            #pragma unroll
            for (int j = 0; j < 4; j++) {
                float p = __expf(s[i][j] - mnew);
                s[i][j] = p;
                rs += p;
            }
            #pragma unroll
            for (int o = 8; o; o >>= 1)
                rs += __shfl_xor_sync(0xffffffffu, rs, o);
            lrow[i] = lrow[i] * corr + rs;
            mrow[i] = mnew;
            #pragma unroll
            for (int j = 0; j < 4; j++) acc[i][j] *= corr;
        }

        __syncthreads();
        #pragma unroll
        for (int i = 0; i < 4; i++)
            #pragma unroll
            for (int j = 0; j < 4; j++)
                Ks[ty * 4 + i][tx * 4 + j] = s[i][j];
        __syncthreads();

        #pragma unroll 8
        for (int k = 0; k < 64; k++) {
            float pv[4], vv[4];
            #pragma unroll
            for (int i = 0; i < 4; i++) pv[i] = Ks[ty * 4 + i][k];
            #pragma unroll
            for (int j = 0; j < 4; j++) vv[j] = Vs[k][tx * 4 + j];
            #pragma unroll
            for (int i = 0; i < 4; i++)
                #pragma unroll
                for (int j = 0; j < 4; j++)
                    acc[i][j] = fmaf(pv[i], vv[j], acc[i][j]);
        }
    }

    #pragma unroll
    for (int i = 0; i < 4; i++) {
        float inv = 1.0f / lrow[i];
        #pragma unroll
        for (int j = 0; j < 4; j++) {
            O[base + (size_t)(q0 + ty * 4 + i) * DM + tx * 4 + j] =
                f_rna_tf32(acc[i][j] * inv);
        }
    }
}

// ---------------------------------------------------------------------------
// Launch
// ---------------------------------------------------------------------------
extern "C" void kernel_launch(void* const* d_in, const int* in_sizes, int n_in,
                              void* d_out, int out_size)
{
    const float* x    = (const float*)d_in[0];
    const int*   mask = (const int*)  d_in[1];
    const float* Wq   = (const float*)d_in[2];
    const float* bq   = (const float*)d_in[3];
    const float* Wk   = (const float*)d_in[4];
    const float* bk   = (const float*)d_in[5];
    const float* Wv   = (const float*)d_in[6];
    const float* bv   = (const float*)d_in[7];
    const float* Wo   = (const float*)d_in[8];
    const float* bo   = (const float*)d_in[9];
    const float* g1   = (const float*)d_in[10];
    const float* be1  = (const float*)d_in[11];
    const float* g2   = (const float*)d_in[12];
    const float* be2  = (const float*)d_in[13];
    const float* W1   = (const float*)d_in[14];
    const float* b1   = (const float*)d_in[15];
    const float* W2   = (const float*)d_in[16];
    const float* b2   = (const float*)d_in[17];
    float* out = (float*)d_out;

    float *h, *q, *k, *v, *att, *ff, *wt;
    cudaGetSymbolAddress((void**)&h,   g_h);
    cudaGetSymbolAddress((void**)&q,   g_q);
    cudaGetSymbolAddress((void**)&k,   g_k);
    cudaGetSymbolAddress((void**)&v,   g_v);
    cudaGetSymbolAddress((void**)&att, g_att);
    cudaGetSymbolAddress((void**)&ff,  g_ff);
    cudaGetSymbolAddress((void**)&wt,  g_wt);

    cudaFuncSetAttribute(gemm_tc_kernel,
        cudaFuncAttributeMaxDynamicSharedMemorySize, SMEM_GEMM);

    // 0. transpose + tf32-round all weights (B operand must be [N][K])
    dim3 tb(32, 8);
    transpose_rna_kernel<<<dim3(512/32,  512/32),  tb>>>(Wq, wt + WT_Q, 512, 512);
    transpose_rna_kernel<<<dim3(512/32,  512/32),  tb>>>(Wk, wt + WT_K, 512, 512);
    transpose_rna_kernel<<<dim3(512/32,  512/32),  tb>>>(Wv, wt + WT_V, 512, 512);
    transpose_rna_kernel<<<dim3(512/32,  512/32),  tb>>>(Wo, wt + WT_O, 512, 512);
    transpose_rna_kernel<<<dim3(2048/32, 512/32),  tb>>>(W1, wt + WT_1, 512, 2048);
    transpose_rna_kernel<<<dim3(512/32,  2048/32), tb>>>(W2, wt + WT_2, 2048, 512);

    // 1. ln1(x) -> h (tf32-rounded)
    layernorm_kernel<<<MTOK, 256>>>(x, g1, be1, h, 1);

    // 2-4. Q/K/V projections (tensor core tf32)
    dim3 gproj(DM / 128, MTOK / 128);
    gemm_tc_kernel<<<gproj, 256, SMEM_GEMM>>>(h, wt + WT_Q, bq, nullptr, q, MTOK, DM, DM, 0);
    gemm_tc_kernel<<<gproj, 256, SMEM_GEMM>>>(h, wt + WT_K, bk, nullptr, k, MTOK, DM, DM, 0);
    gemm_tc_kernel<<<gproj, 256, SMEM_GEMM>>>(h, wt + WT_V, bv, nullptr, v, MTOK, DM, DM, 0);

    // 5. causal attention -> att (tf32-rounded)
    dim3 gattn(LSEQ / 64, NH, BATCH);
    attn_kernel<<<gattn, 256>>>(q, k, v, mask, att);

    // 6. O projection + residual(x) -> out
    gemm_tc_kernel<<<gproj, 256, SMEM_GEMM>>>(att, wt + WT_O, bo, x, out, MTOK, DM, DM, 2);

    // 7. ln2(out) -> h (tf32-rounded)
    layernorm_kernel<<<MTOK, 256>>>(out, g2, be2, h, 1);

    // 8. FFN1 + GELU -> ff (tf32-rounded)
    dim3 gff1(DFF / 128, MTOK / 128);
    gemm_tc_kernel<<<gff1, 256, SMEM_GEMM>>>(h, wt + WT_1, b1, nullptr, ff, MTOK, DFF, DM, 1);

    // 9. FFN2 + residual -> out
    dim3 gff2(DM / 128, MTOK / 128);
    gemm_tc_kernel<<<gff2, 256, SMEM_GEMM>>>(ff, wt + WT_2, b2, out, out, MTOK, DM, DFF, 2);
}

// round 5
// speedup vs baseline: 2.9657x; 1.5672x over previous
#include <cuda_runtime.h>
#include <cstdint>
#include <math.h>

#define DM    512
#define DFF   2048
#define BATCH 4
#define LSEQ  2048
#define MTOK  (BATCH * LSEQ)   // 8192 rows
#define NH    8
#define DK    64
#define EPSLN 1e-5f

// ---------------------------------------------------------------------------
// Scratch (device globals: allocation-free per harness rules)
// ---------------------------------------------------------------------------
__device__ float g_h  [(size_t)MTOK * DM];    // layernorm outputs (tf32-rounded)
__device__ float g_q  [(size_t)MTOK * DM];
__device__ float g_k  [(size_t)MTOK * DM];
__device__ float g_v  [(size_t)MTOK * DM];
__device__ float g_att[(size_t)MTOK * DM];    // attention out (tf32-rounded)
__device__ float g_ff [(size_t)MTOK * DFF];   // gelu out (tf32-rounded)
__device__ float g_wt [4 * 512 * 512 + 2 * 512 * 2048];

#define WT_Q  0
#define WT_K  (512*512)
#define WT_V  (2*512*512)
#define WT_O  (3*512*512)
#define WT_1  (4*512*512)
#define WT_2  (4*512*512 + 512*2048)

// ---------------------------------------------------------------------------
// PTX helpers (baseline PTX only: works under compute_103 target)
// ---------------------------------------------------------------------------
__device__ __forceinline__ uint32_t smem_u32(const void* p) {
    uint32_t a;
    asm("{ .reg .u64 t; cvta.to.shared.u64 t, %1; cvt.u32.u64 %0, t; }" : "=r"(a) : "l"(p));
    return a;
}
__device__ __forceinline__ float f_rna_tf32(float x) {
    uint32_t u;
    asm("cvt.rna.tf32.f32 %0, %1;" : "=r"(u) : "f"(x));
    return __uint_as_float(u);
}

#define CP_ASYNC16(dst, src) \
    asm volatile("cp.async.cg.shared.global [%0], [%1], 16;" :: "r"(dst), "l"(src))
#define CP_COMMIT() asm volatile("cp.async.commit_group;" ::: "memory")
#define CP_WAIT1()  asm volatile("cp.async.wait_group 1;" ::: "memory")

__device__ __forceinline__ void mma_tf32(
    float& d0, float& d1, float& d2, float& d3,
    uint32_t a0, uint32_t a1, uint32_t a2, uint32_t a3,
    uint32_t b0, uint32_t b1)
{
    asm volatile(
        "mma.sync.aligned.m16n8k8.row.col.f32.tf32.tf32.f32 "
        "{%0,%1,%2,%3}, {%4,%5,%6,%7}, {%8,%9}, {%0,%1,%2,%3};"
        : "+f"(d0), "+f"(d1), "+f"(d2), "+f"(d3)
        : "r"(a0), "r"(a1), "r"(a2), "r"(a3), "r"(b0), "r"(b1));
}

__device__ __forceinline__ float gelu_exact(float x) {
    return 0.5f * x * (1.0f + erff(x * 0.70710678118654752440f));
}

// exp(x) for x <= 0 via FMA-pipe polynomial (avoids MUFU throughput wall).
// exp(x) = 2^(x*log2e); z split into int+frac; 2^f by degree-6 Taylor.
__device__ __forceinline__ float exp_fast(float x) {
    float z = x * 1.44269504088896341f;
    z = fmaxf(z, -126.0f);
    float n = floorf(z);
    float f = z - n;
    float p = fmaf(f, 1.54035304e-4f, 0.00133335581f);
    p = fmaf(f, p, 0.00961812911f);
    p = fmaf(f, p, 0.0555041087f);
    p = fmaf(f, p, 0.2402265070f);
    p = fmaf(f, p, 0.69314718056f);
    p = fmaf(f, p, 1.0f);
    return p * __int_as_float(((int)n + 127) << 23);
}

// ---------------------------------------------------------------------------
// LayerNorm: one block (256 threads) per row of 512. rnd=1 -> tf32-round out.
// ---------------------------------------------------------------------------
__global__ __launch_bounds__(256) void layernorm_kernel(
    const float* __restrict__ x, const float* __restrict__ g,
    const float* __restrict__ be, float* __restrict__ out, int rnd)
{
    __shared__ float red[8];
    __shared__ float statv;
    int row = blockIdx.x;
    int t = threadIdx.x;
    const float* xr = x + (size_t)row * DM;

    float v0 = xr[t];
    float v1 = xr[t + 256];

    float s = v0 + v1;
    #pragma unroll
    for (int o = 16; o; o >>= 1) s += __shfl_xor_sync(0xffffffffu, s, o);
    if ((t & 31) == 0) red[t >> 5] = s;
    __syncthreads();
    if (t == 0) {
        float tot = 0.f;
        #pragma unroll
        for (int i = 0; i < 8; i++) tot += red[i];
        statv = tot * (1.0f / DM);
    }
    __syncthreads();
    float mu = statv;
    __syncthreads();

    float d0 = v0 - mu, d1 = v1 - mu;
    s = d0 * d0 + d1 * d1;
    #pragma unroll
    for (int o = 16; o; o >>= 1) s += __shfl_xor_sync(0xffffffffu, s, o);
    if ((t & 31) == 0) red[t >> 5] = s;
    __syncthreads();
    if (t == 0) {
        float tot = 0.f;
        #pragma unroll
        for (int i = 0; i < 8; i++) tot += red[i];
        statv = rsqrtf(tot * (1.0f / DM) + EPSLN);
    }
    __syncthreads();
    float rs = statv;

    float o0 = d0 * rs * g[t]       + be[t];
    float o1 = d1 * rs * g[t + 256] + be[t + 256];
    if (rnd) { o0 = f_rna_tf32(o0); o1 = f_rna_tf32(o1); }
    float* orow = out + (size_t)row * DM;
    orow[t]       = o0;
    orow[t + 256] = o1;
}

// ---------------------------------------------------------------------------
// Weight transpose + round-to-tf32.  in: [R][C] -> out: [C][R]
// ---------------------------------------------------------------------------
__global__ __launch_bounds__(256) void transpose_rna_kernel(
    const float* __restrict__ in, float* __restrict__ out, int R, int C)
{
    __shared__ float t[32][33];
    int bx = blockIdx.x * 32;
    int by = blockIdx.y * 32;
    int txl = threadIdx.x, tyl = threadIdx.y;
    #pragma unroll
    for (int i = 0; i < 32; i += 8)
        t[tyl + i][txl] = in[(size_t)(by + tyl + i) * C + bx + txl];
    __syncthreads();
    #pragma unroll
    for (int i = 0; i < 32; i += 8)
        out[(size_t)(bx + tyl + i) * R + by + txl] = f_rna_tf32(t[txl][tyl + i]);
}

// ---------------------------------------------------------------------------
// Tensor-core tf32 GEMM (unchanged from R4)
// ---------------------------------------------------------------------------
#define ROWPAD 36
#define STG_FLOATS (128 * ROWPAD)
#define SMEM_GEMM (2 * 2 * STG_FLOATS * 4)

__global__ __launch_bounds__(256, 2) void gemm_tc_kernel(
    const float* __restrict__ A, const float* __restrict__ BT,
    const float* __restrict__ bias, const float* __restrict__ res,
    float* __restrict__ C, int M, int N, int K, int mode)
{
    extern __shared__ float smem[];
    const uint32_t sb = smem_u32(smem);
    const int tid = threadIdx.x;
    const int wid = tid >> 5;
    const int lid = tid & 31;
    const int g = lid >> 2;
    const int t = lid & 3;
    const int bm = blockIdx.y * 128;
    const int bn = blockIdx.x * 128;
    const int m_off = (wid & 1) * 64;
    const int n_off = (wid >> 1) * 32;
    const int nchunk = K >> 5;

    float d[4][4][4];
    #pragma unroll
    for (int mf = 0; mf < 4; mf++)
        #pragma unroll
        for (int nf = 0; nf < 4; nf++)
            #pragma unroll
            for (int r = 0; r < 4; r++) d[mf][nf][r] = 0.f;

    auto issue = [&](int c, int s) {
        const int k0 = c << 5;
        const uint32_t sbase = sb + (uint32_t)(s * 2 * STG_FLOATS) * 4u;
        #pragma unroll
        for (int it = 0; it < 8; it++) {
            int u = it * 256 + tid;
            int op = u >> 10;
            int v = u & 1023;
            int row = v >> 3;
            int c4 = v & 7;
            const float* src = op
                ? (BT + (size_t)(bn + row) * K + k0 + (c4 << 2))
                : (A  + (size_t)(bm + row) * K + k0 + (c4 << 2));
            uint32_t dst = sbase + (uint32_t)(op * STG_FLOATS + row * ROWPAD + (c4 << 2)) * 4u;
            CP_ASYNC16(dst, src);
        }
    };

    issue(0, 0);
    CP_COMMIT();

    int buf = 0;
    for (int c = 0; c < nchunk; c++) {
        if (c + 1 < nchunk) issue(c + 1, buf ^ 1);
        CP_COMMIT();
        CP_WAIT1();
        __syncthreads();

        const uint32_t* sAu = (const uint32_t*)smem + buf * 2 * STG_FLOATS;
        const uint32_t* sBu = sAu + STG_FLOATS;
        const int arow = (m_off + g) * ROWPAD + t;
        const int brow = (n_off + g) * ROWPAD + t;

        #pragma unroll
        for (int kk = 0; kk < 32; kk += 8) {
            uint32_t a[4][4], b[4][2];
            #pragma unroll
            for (int mf = 0; mf < 4; mf++) {
                int base = arow + mf * 16 * ROWPAD + kk;
                a[mf][0] = sAu[base];
                a[mf][1] = sAu[base + 8 * ROWPAD];
                a[mf][2] = sAu[base + 4];
                a[mf][3] = sAu[base + 8 * ROWPAD + 4];
            }
            #pragma unroll
            for (int nf = 0; nf < 4; nf++) {
                int base = brow + nf * 8 * ROWPAD + kk;
                b[nf][0] = sBu[base];
                b[nf][1] = sBu[base + 4];
            }
            #pragma unroll
            for (int mf = 0; mf < 4; mf++)
                #pragma unroll
                for (int nf = 0; nf < 4; nf++)
                    mma_tf32(d[mf][nf][0], d[mf][nf][1], d[mf][nf][2], d[mf][nf][3],
                             a[mf][0], a[mf][1], a[mf][2], a[mf][3],
                             b[nf][0], b[nf][1]);
        }
        __syncthreads();
        buf ^= 1;
    }

    #pragma unroll
    for (int nf = 0; nf < 4; nf++) {
        int col = bn + n_off + nf * 8 + 2 * t;
        float2 bi = *reinterpret_cast<const float2*>(bias + col);
        #pragma unroll
        for (int mf = 0; mf < 4; mf++) {
            int r0 = bm + m_off + mf * 16 + g;
            #pragma unroll
            for (int half = 0; half < 2; half++) {
                int r = r0 + half * 8;
                float v0 = d[mf][nf][half * 2 + 0] + bi.x;
                float v1 = d[mf][nf][half * 2 + 1] + bi.y;
                if (mode == 1) {
                    v0 = f_rna_tf32(gelu_exact(v0));
                    v1 = f_rna_tf32(gelu_exact(v1));
                } else if (mode == 2) {
                    float2 rv = *reinterpret_cast<const float2*>(
                        res + (size_t)r * N + col);
                    v0 += rv.x; v1 += rv.y;
                }
                float2 o; o.x = v0; o.y = v1;
                *reinterpret_cast<float2*>(C + (size_t)r * N + col) = o;
            }
        }
    }
}

// ---------------------------------------------------------------------------
// Tensor-core causal flash attention.
// CTA = 128 queries x one (b,h). 8 warps, each owns 16 query rows.
// K-blocks of 64 keys. QK^T and PV via m16n8k8 tf32 mma; softmax exp via
// FMA-pipe polynomial (exp_fast). Smem pads chosen for conflict-free frags.
// ---------------------------------------------------------------------------
#define KS_PAD 76
#define VS_PAD 68
#define PS_PAD 76
#define KS_OFF 0
#define VS_OFF (64 * KS_PAD)                       // 4864
#define PS_OFF (VS_OFF + 64 * VS_PAD)              // 9216
#define MK_OFF (PS_OFF + 128 * PS_PAD)             // 18944 floats
#define SMEM_ATTN ((MK_OFF + 64) * 4)              // 76032 bytes

__global__ __launch_bounds__(256) void attn_tc_kernel(
    const float* __restrict__ Q, const float* __restrict__ K,
    const float* __restrict__ V, const int* __restrict__ mask,
    float* __restrict__ O)
{
    extern __shared__ float sm[];
    float* Ks = sm + KS_OFF;
    float* Vs = sm + VS_OFF;
    float* Ps = sm + PS_OFF;          // doubles as Q staging [128][PS_PAD]
    int*   mk = (int*)(sm + MK_OFF);

    const int qt = (int)gridDim.x - 1 - (int)blockIdx.x;   // heavy tiles first
    const int h = blockIdx.y, b = blockIdx.z;
    const int q0 = qt * 128;
    const int tid = threadIdx.x;
    const int w = tid >> 5;
    const int lid = tid & 31;
    const int g = lid >> 2;
    const int t = lid & 3;
    const size_t base = (size_t)b * LSEQ * DM + (size_t)h * DK;

    // ---- stage Q tile into Ps [128][PS_PAD], rna-rounded ----
    #pragma unroll
    for (int it = 0; it < 8; it++) {
        int li = it * 256 + tid;          // float4 index over 128x16
        int r = li >> 4;
        int c = (li & 15) << 2;
        float4 v = *reinterpret_cast<const float4*>(
            Q + base + (size_t)(q0 + r) * DM + c);
        float* d = Ps + r * PS_PAD + c;
        d[0] = f_rna_tf32(v.x); d[1] = f_rna_tf32(v.y);
        d[2] = f_rna_tf32(v.z); d[3] = f_rna_tf32(v.w);
    }
    __syncthreads();

    // ---- Q fragments to registers: 8 k-steps x 4 regs ----
    uint32_t qf[8][4];
    {
        const float* Pw = Ps + (w * 16) * PS_PAD;
        #pragma unroll
        for (int ks = 0; ks < 8; ks++) {
            int ko = ks * 8;
            qf[ks][0] = __float_as_uint(Pw[ g      * PS_PAD + ko + t]);
            qf[ks][1] = __float_as_uint(Pw[(g + 8) * PS_PAD + ko + t]);
            qf[ks][2] = __float_as_uint(Pw[ g      * PS_PAD + ko + t + 4]);
            qf[ks][3] = __float_as_uint(Pw[(g + 8) * PS_PAD + ko + t + 4]);
        }
    }
    __syncthreads();

    float acc[8][4];
    #pragma unroll
    for (int nf = 0; nf < 8; nf++)
        #pragma unroll
        for (int r = 0; r < 4; r++) acc[nf][r] = 0.f;
    float m_lo = -1e30f, m_hi = -1e30f, l_lo = 0.f, l_hi = 0.f;

    const int row_lo = q0 + w * 16 + g;
    const int row_hi = row_lo + 8;
    float* Pw = Ps + (w * 16) * PS_PAD;
    const int nkb = 2 * qt + 2;

    for (int kb = 0; kb < nkb; kb++) {
        const int k0 = kb * 64;

        // ---- load K,V block (rna-rounded), mask ----
        #pragma unroll
        for (int it = 0; it < 4; it++) {
            int li = it * 256 + tid;      // float4 over 64x16
            int r = li >> 4;
            int c = (li & 15) << 2;
            float4 kv = *reinterpret_cast<const float4*>(
                K + base + (size_t)(k0 + r) * DM + c);
            float4 vv = *reinterpret_cast<const float4*>(
                V + base + (size_t)(k0 + r) * DM + c);
            float* dk = Ks + r * KS_PAD + c;
            dk[0] = f_rna_tf32(kv.x); dk[1] = f_rna_tf32(kv.y);
            dk[2] = f_rna_tf32(kv.z); dk[3] = f_rna_tf32(kv.w);
            float* dv = Vs + r * VS_PAD + c;
            dv[0] = f_rna_tf32(vv.x); dv[1] = f_rna_tf32(vv.y);
            dv[2] = f_rna_tf32(vv.z); dv[3] = f_rna_tf32(vv.w);
        }
        if (tid < 64) mk[tid] = mask[b * LSEQ + k0 + tid];
        __syncthreads();

        // ---- S = Q K^T ----
        float s[8][4];
        #pragma unroll
        for (int nf = 0; nf < 8; nf++)
            #pragma unroll
            for (int r = 0; r < 4; r++) s[nf][r] = 0.f;

        #pragma unroll
        for (int ks = 0; ks < 8; ks++) {
            int ko = ks * 8;
            #pragma unroll
            for (int nf = 0; nf < 8; nf++) {
                uint32_t b0 = __float_as_uint(Ks[(nf * 8 + g) * KS_PAD + ko + t]);
                uint32_t b1 = __float_as_uint(Ks[(nf * 8 + g) * KS_PAD + ko + t + 4]);
                mma_tf32(s[nf][0], s[nf][1], s[nf][2], s[nf][3],
                         qf[ks][0], qf[ks][1], qf[ks][2], qf[ks][3], b0, b1);
            }
        }

        // ---- scale + causal + pad mask ----
        #pragma unroll
        for (int nf = 0; nf < 8; nf++) {
            int cl = nf * 8 + 2 * t;
            int key0 = k0 + cl;
            int key1 = key0 + 1;
            int m0 = mk[cl];
            int m1 = mk[cl + 1];
            s[nf][0] = (key0 > row_lo || m0 == 0) ? -1e9f : s[nf][0] * 0.125f;
            s[nf][1] = (key1 > row_lo || m1 == 0) ? -1e9f : s[nf][1] * 0.125f;
            s[nf][2] = (key0 > row_hi || m0 == 0) ? -1e9f : s[nf][2] * 0.125f;
            s[nf][3] = (key1 > row_hi || m1 == 0) ? -1e9f : s[nf][3] * 0.125f;
        }

        // ---- online softmax ----
        float bm_lo = s[0][0], bm_hi = s[0][2];
        #pragma unroll
        for (int nf = 0; nf < 8; nf++) {
            bm_lo = fmaxf(bm_lo, fmaxf(s[nf][0], s[nf][1]));
            bm_hi = fmaxf(bm_hi, fmaxf(s[nf][2], s[nf][3]));
        }
        bm_lo = fmaxf(bm_lo, __shfl_xor_sync(0xffffffffu, bm_lo, 1));
        bm_lo = fmaxf(bm_lo, __shfl_xor_sync(0xffffffffu, bm_lo, 2));
        bm_hi = fmaxf(bm_hi, __shfl_xor_sync(0xffffffffu, bm_hi, 1));
        bm_hi = fmaxf(bm_hi, __shfl_xor_sync(0xffffffffu, bm_hi, 2));

        float mn_lo = fmaxf(m_lo, bm_lo);
        float mn_hi = fmaxf(m_hi, bm_hi);
        float co_lo = exp_fast(m_lo - mn_lo);
        float co_hi = exp_fast(m_hi - mn_hi);

        float sum_lo = 0.f, sum_hi = 0.f;
        #pragma unroll
        for (int nf = 0; nf < 8; nf++) {
            s[nf][0] = exp_fast(s[nf][0] - mn_lo);
            s[nf][1] = exp_fast(s[nf][1] - mn_lo);
            s[nf][2] = exp_fast(s[nf][2] - mn_hi);
            s[nf][3] = exp_fast(s[nf][3] - mn_hi);
            sum_lo += s[nf][0] + s[nf][1];
            sum_hi += s[nf][2] + s[nf][3];
        }
        sum_lo += __shfl_xor_sync(0xffffffffu, sum_lo, 1);
        sum_lo += __shfl_xor_sync(0xffffffffu, sum_lo, 2);
        sum_hi += __shfl_xor_sync(0xffffffffu, sum_hi, 1);
        sum_hi += __shfl_xor_sync(0xffffffffu, sum_hi, 2);

        l_lo = l_lo * co_lo + sum_lo;
        l_hi = l_hi * co_hi + sum_hi;
        m_lo = mn_lo; m_hi = mn_hi;
        #pragma unroll
        for (int nf = 0; nf < 8; nf++) {
            acc[nf][0] *= co_lo; acc[nf][1] *= co_lo;
            acc[nf][2] *= co_hi; acc[nf][3] *= co_hi;
        }

        // ---- stage P into warp-private smem (rna-rounded) ----
        #pragma unroll
        for (int nf = 0; nf < 8; nf++) {
            int cl = nf * 8 + 2 * t;
            Pw[ g      * PS_PAD + cl    ] = f_rna_tf32(s[nf][0]);
            Pw[ g      * PS_PAD + cl + 1] = f_rna_tf32(s[nf][1]);
            Pw[(g + 8) * PS_PAD + cl    ] = f_rna_tf32(s[nf][2]);
            Pw[(g + 8) * PS_PAD + cl + 1] = f_rna_tf32(s[nf][3]);
        }
        __syncwarp();

        // ---- acc += P V ----
        #pragma unroll
        for (int ks = 0; ks < 8; ks++) {
            int ko = ks * 8;
            uint32_t a0 = __float_as_uint(Pw[ g      * PS_PAD + ko + t]);
            uint32_t a1 = __float_as_uint(Pw[(g + 8) * PS_PAD + ko + t]);
            uint32_t a2 = __float_as_uint(Pw[ g      * PS_PAD + ko + t + 4]);
            uint32_t a3 = __float_as_uint(Pw[(g + 8) * PS_PAD + ko + t + 4]);
            #pragma unroll
            for (int nf = 0; nf < 8; nf++) {
                uint32_t b0 = __float_as_uint(Vs[(ko + t)     * VS_PAD + nf * 8 + g]);
                uint32_t b1 = __float_as_uint(Vs[(ko + t + 4) * VS_PAD + nf * 8 + g]);
                mma_tf32(acc[nf][0], acc[nf][1], acc[nf][2], acc[nf][3],
                         a0, a1, a2, a3, b0, b1);
            }
        }
        __syncthreads();   // all warps done with Ks/Vs before next block load
    }

    // ---- epilogue: normalize, rna-round, write ----
    float inv_lo = 1.0f / l_lo;
    float inv_hi = 1.0f / l_hi;
    #pragma unroll
    for (int nf = 0; nf < 8; nf++) {
        int cl = nf * 8 + 2 * t;
        float2 o;
        o.x = f_rna_tf32(acc[nf][0] * inv_lo);
        o.y = f_rna_tf32(acc[nf][1] * inv_lo);
        *reinterpret_cast<float2*>(O + base + (size_t)row_lo * DM + cl) = o;
        o.x = f_rna_tf32(acc[nf][2] * inv_hi);
        o.y = f_rna_tf32(acc[nf][3] * inv_hi);
        *reinterpret_cast<float2*>(O + base + (size_t)row_hi * DM + cl) = o;
    }
}

// ---------------------------------------------------------------------------
// Launch
// ---------------------------------------------------------------------------
extern "C" void kernel_launch(void* const* d_in, const int* in_sizes, int n_in,
                              void* d_out, int out_size)
{
    const float* x    = (const float*)d_in[0];
    const int*   mask = (const int*)  d_in[1];
    const float* Wq   = (const float*)d_in[2];
    const float* bq   = (const float*)d_in[3];
    const float* Wk   = (const float*)d_in[4];
    const float* bk   = (const float*)d_in[5];
    const float* Wv   = (const float*)d_in[6];
    const float* bv   = (const float*)d_in[7];
    const float* Wo   = (const float*)d_in[8];
    const float* bo   = (const float*)d_in[9];
    const float* g1   = (const float*)d_in[10];
    const float* be1  = (const float*)d_in[11];
    const float* g2   = (const float*)d_in[12];
    const float* be2  = (const float*)d_in[13];
    const float* W1   = (const float*)d_in[14];
    const float* b1   = (const float*)d_in[15];
    const float* W2   = (const float*)d_in[16];
    const float* b2   = (const float*)d_in[17];
    float* out = (float*)d_out;

    float *h, *q, *k, *v, *att, *ff, *wt;
    cudaGetSymbolAddress((void**)&h,   g_h);
    cudaGetSymbolAddress((void**)&q,   g_q);
    cudaGetSymbolAddress((void**)&k,   g_k);
    cudaGetSymbolAddress((void**)&v,   g_v);
    cudaGetSymbolAddress((void**)&att, g_att);
    cudaGetSymbolAddress((void**)&ff,  g_ff);
    cudaGetSymbolAddress((void**)&wt,  g_wt);

    cudaFuncSetAttribute(gemm_tc_kernel,
        cudaFuncAttributeMaxDynamicSharedMemorySize, SMEM_GEMM);
    cudaFuncSetAttribute(attn_tc_kernel,
        cudaFuncAttributeMaxDynamicSharedMemorySize, SMEM_ATTN);

    // 0. transpose + tf32-round all weights
    dim3 tb(32, 8);
    transpose_rna_kernel<<<dim3(512/32,  512/32),  tb>>>(Wq, wt + WT_Q, 512, 512);
    transpose_rna_kernel<<<dim3(512/32,  512/32),  tb>>>(Wk, wt + WT_K, 512, 512);
    transpose_rna_kernel<<<dim3(512/32,  512/32),  tb>>>(Wv, wt + WT_V, 512, 512);
    transpose_rna_kernel<<<dim3(512/32,  512/32),  tb>>>(Wo, wt + WT_O, 512, 512);
    transpose_rna_kernel<<<dim3(2048/32, 512/32),  tb>>>(W1, wt + WT_1, 512, 2048);
    transpose_rna_kernel<<<dim3(512/32,  2048/32), tb>>>(W2, wt + WT_2, 2048, 512);

    // 1. ln1(x) -> h
    layernorm_kernel<<<MTOK, 256>>>(x, g1, be1, h, 1);

    // 2-4. Q/K/V projections
    dim3 gproj(DM / 128, MTOK / 128);
    gemm_tc_kernel<<<gproj, 256, SMEM_GEMM>>>(h, wt + WT_Q, bq, nullptr, q, MTOK, DM, DM, 0);
    gemm_tc_kernel<<<gproj, 256, SMEM_GEMM>>>(h, wt + WT_K, bk, nullptr, k, MTOK, DM, DM, 0);
    gemm_tc_kernel<<<gproj, 256, SMEM_GEMM>>>(h, wt + WT_V, bv, nullptr, v, MTOK, DM, DM, 0);

    // 5. causal attention (tensor core)
    dim3 gattn(LSEQ / 128, NH, BATCH);
    attn_tc_kernel<<<gattn, 256, SMEM_ATTN>>>(q, k, v, mask, att);

    // 6. O projection + residual(x) -> out
    gemm_tc_kernel<<<gproj, 256, SMEM_GEMM>>>(att, wt + WT_O, bo, x, out, MTOK, DM, DM, 2);

    // 7. ln2(out) -> h
    layernorm_kernel<<<MTOK, 256>>>(out, g2, be2, h, 1);

    // 8. FFN1 + GELU -> ff
    dim3 gff1(DFF / 128, MTOK / 128);
    gemm_tc_kernel<<<gff1, 256, SMEM_GEMM>>>(h, wt + WT_1, b1, nullptr, ff, MTOK, DFF, DM, 1);

    // 9. FFN2 + residual -> out
    dim3 gff2(DM / 128, MTOK / 128);
    gemm_tc_kernel<<<gff2, 256, SMEM_GEMM>>>(ff, wt + WT_2, b2, out, out, MTOK, DM, DFF, 2);
}